// round 6
// baseline (speedup 1.0000x reference)
#include <cuda_runtime.h>
#include <math.h>

// Problem constants
#define Bc 16
#define Ac 3
#define Cc 80
#define Hc 76
#define Wc 76
#define Tc 50
#define Sc (Hc * Wc)            // 5776
#define NCELL (Bc * Ac * Sc)    // 277248
#define NCH 85
#define TPB 256
#define NBLK ((NCELL + TPB - 1) / TPB)   // 1083

// Scratch (device globals, no allocation)
__device__ __align__(16) unsigned char g_mask[NCELL];
__device__ __align__(16) unsigned char g_noobj0[NCELL];   // 1 => noobj forced to 0
__device__ float g_tx[NCELL];
__device__ float g_ty[NCELL];
__device__ float g_tw[NCELL];
__device__ float g_th[NCELL];
__device__ unsigned g_cls[NCELL * 3];                     // class bitmask, lazily cleared
__device__ float g_part[NBLK * 16];                       // per-block partial sums (9 used)

// clip(log(p), min=-100). logf(0) = -inf -> clamps to -100.
__device__ __forceinline__ float clipl(float p) {
    float l = logf(p);
    return l < -100.0f ? -100.0f : l;
}
__device__ __forceinline__ float bcef(float p, float t) {
    return -(t * clipl(p) + (1.0f - t) * clipl(1.0f - p));
}
__device__ __forceinline__ float sigf(float v) {
    return 1.0f / (1.0f + expf(-v));
}

// ---------------------------------------------------------------------------
// Kernel 1: zero the per-launch byte arrays (mask, noobj0). 2*277248 bytes.
// ---------------------------------------------------------------------------
__global__ void yolo_zero_kernel() {
    int i = blockIdx.x * blockDim.x + threadIdx.x;
    const int n16 = NCELL / 16;  // 17328, exact
    if (i < n16) {
        int4 z = make_int4(0, 0, 0, 0);
        reinterpret_cast<int4*>(g_mask)[i] = z;
        reinterpret_cast<int4*>(g_noobj0)[i] = z;
    }
}

// ---------------------------------------------------------------------------
// Kernel 2: build targets. One thread per batch, serial over t (last-wins
// matches XLA serial scatter-set order). Cells are disjoint across batches
// (flat index contains b), so no atomics needed.
// ---------------------------------------------------------------------------
__global__ void yolo_build_kernel(const float* __restrict__ tgt) {
    int b = threadIdx.x;
    if (b >= Bc) return;

    // SA = ANCHORS / (608/76) = ANCHORS / 8  (exact in binary)
    const float aw[3] = {1.25f, 2.0f, 4.125f};
    const float ah[3] = {1.625f, 3.75f, 2.875f};

    for (int t = 0; t < Tc; t++) {
        const float* r = tgt + (size_t)(b * Tc + t) * 5;
        float c0 = r[0], c1 = r[1], c2 = r[2], c3 = r[3], c4 = r[4];
        if ((c0 + c1 + c2 + c3 + c4) == 0.0f) continue;  // valid check

        int   cls = (int)c0;
        float gx = c1 * (float)Wc;
        float gy = c2 * (float)Hc;
        float gw = c3 * (float)Wc;
        float gh = c4 * (float)Hc;
        int gi = (int)gx;
        int gj = (int)gy;

        // IoU vs anchors (shifted by +1 as in reference), argmax first-max-wins
        float a1 = (gw + 1.0f) * (gh + 1.0f);
        float iou[3];
        int best = 0;
        #pragma unroll
        for (int a = 0; a < 3; a++) {
            float iw = fminf(gw, aw[a]) + 1.0f; iw = fmaxf(iw, 0.0f);
            float ih = fminf(gh, ah[a]) + 1.0f; ih = fmaxf(ih, 0.0f);
            float inter = iw * ih;
            float a2 = (aw[a] + 1.0f) * (ah[a] + 1.0f);
            iou[a] = inter / (a1 + a2 - inter + 1e-16f);
            if (iou[a] > iou[best]) best = a;
        }

        // noobj suppression: valid & iou > 0.5 (drop-mode flat bounds)
        #pragma unroll
        for (int a = 0; a < 3; a++) {
            if (iou[a] > 0.5f) {
                long long idx = (((long long)(b * Ac + a) * Hc + gj) * Wc + gi);
                if (idx >= 0 && idx < NCELL) g_noobj0[idx] = 1;
            }
        }

        // positive assignment (ok = valid & gj<H & gi<W; drop-mode flat bounds)
        if (gj < Hc && gi < Wc) {
            long long cell = (((long long)(b * Ac + best) * Hc + gj) * Wc + gi);
            if (cell >= 0 && cell < NCELL) {
                int ci = (int)cell;
                if (!g_mask[ci]) {  // lazy-clear class bits on first hit this launch
                    g_mask[ci] = 1;
                    g_cls[ci * 3 + 0] = 0u;
                    g_cls[ci * 3 + 1] = 0u;
                    g_cls[ci * 3 + 2] = 0u;
                }
                g_tx[ci] = gx - (float)gi;
                g_ty[ci] = gy - (float)gj;
                g_tw[ci] = logf(gw / aw[best] + 1e-16f);
                g_th[ci] = logf(gh / ah[best] + 1e-16f);
                long long cidx = cell * Cc + cls;
                if (cidx >= 0 && cidx < (long long)NCELL * Cc && cls >= 0 && cls < Cc)
                    g_cls[ci * 3 + (cls >> 5)] |= (1u << (cls & 31));
            }
        }
    }
}

// ---------------------------------------------------------------------------
// Kernel 3: main reduction. One thread per cell.
// Only channel 4 (conf) is read at every cell; channels 0-3 and 5-84 are
// read only at the ~800 masked cells. Deterministic block-tree reduce.
// Partial slots: 0=sum_noobj_bce 1=n_noobj 2=sum_x 3=sum_y 4=sum_w 5=sum_h
//                6=sum_conf_obj 7=sum_cls 8=n_mask
// ---------------------------------------------------------------------------
__global__ void yolo_main_kernel(const float* __restrict__ inp) {
    int i = blockIdx.x * TPB + threadIdx.x;
    float v[9];
    #pragma unroll
    for (int k = 0; k < 9; k++) v[k] = 0.0f;

    if (i < NCELL) {
        int g  = i / Sc;         // b*A + a
        int hw = i - g * Sc;
        const float* base = inp + (size_t)g * NCH * Sc + hw;

        float conf = sigf(base[4 * Sc]);

        if (!g_noobj0[i]) {               // noobj = 1 here
            v[0] = -clipl(1.0f - conf);   // bce(conf, 0)
            v[1] = 1.0f;
        }
        if (g_mask[i]) {
            v[8] = 1.0f;
            float p0 = base[0];
            float p1 = base[Sc];
            float p2 = base[2 * Sc];
            float p3 = base[3 * Sc];
            v[2] = bcef(sigf(p0), g_tx[i]);
            v[3] = bcef(sigf(p1), g_ty[i]);
            float dw = p2 - g_tw[i]; v[4] = dw * dw;
            float dh = p3 - g_th[i]; v[5] = dh * dh;
            v[6] = -clipl(conf);          // bce(conf, 1)

            unsigned cb0 = g_cls[i * 3 + 0];
            unsigned cb1 = g_cls[i * 3 + 1];
            unsigned cb2 = g_cls[i * 3 + 2];
            float sc = 0.0f;
            #pragma unroll 4
            for (int c = 0; c < Cc; c++) {
                float pc = sigf(base[(5 + c) * Sc]);
                unsigned word = (c < 32) ? cb0 : (c < 64) ? cb1 : cb2;
                float tc = ((word >> (c & 31)) & 1u) ? 1.0f : 0.0f;
                sc += bcef(pc, tc);
            }
            v[7] = sc;
        }
    }

    __shared__ float sh[TPB];
    #pragma unroll
    for (int k = 0; k < 9; k++) {
        sh[threadIdx.x] = v[k];
        __syncthreads();
        for (int s = TPB / 2; s > 0; s >>= 1) {
            if (threadIdx.x < s) sh[threadIdx.x] += sh[threadIdx.x + s];
            __syncthreads();
        }
        if (threadIdx.x == 0) g_part[blockIdx.x * 16 + k] = sh[0];
        __syncthreads();
    }
}

// ---------------------------------------------------------------------------
// Kernel 4: final deterministic reduce over per-block partials + loss math.
// ---------------------------------------------------------------------------
__global__ void yolo_final_kernel(float* __restrict__ out, int out_size) {
    float acc[9];
    #pragma unroll
    for (int k = 0; k < 9; k++) acc[k] = 0.0f;
    for (int j = threadIdx.x; j < NBLK; j += 256) {
        #pragma unroll
        for (int k = 0; k < 9; k++) acc[k] += g_part[j * 16 + k];
    }

    __shared__ float sh[256];
    float tot[9];
    #pragma unroll
    for (int k = 0; k < 9; k++) {
        sh[threadIdx.x] = acc[k];
        __syncthreads();
        for (int s = 128; s > 0; s >>= 1) {
            if (threadIdx.x < s) sh[threadIdx.x] += sh[threadIdx.x + s];
            __syncthreads();
        }
        tot[k] = sh[0];
        __syncthreads();
    }

    if (threadIdx.x == 0) {
        const float N = (float)NCELL;
        float n_m  = tot[8];
        float n_nm = tot[1];
        float loss_x = tot[2] / N / n_m;
        float loss_y = tot[3] / N / n_m;
        float loss_w = tot[4] / N / n_m;
        float loss_h = tot[5] / N / n_m;
        float loss_conf = tot[6] / N / n_m + 0.5f * tot[0] / N / n_nm;
        float loss_cls  = tot[7] / (n_m * (float)Cc) / n_m;
        float loss = 2.5f * (loss_x + loss_y) + 2.5f * (loss_w + loss_h)
                   + loss_conf + loss_cls;
        float res[7] = {loss, loss_x, loss_y, loss_w, loss_h, loss_conf, loss_cls};
        for (int k = 0; k < 7 && k < out_size; k++) out[k] = res[k];
    }
}

// ---------------------------------------------------------------------------
extern "C" void kernel_launch(void* const* d_in, const int* in_sizes, int n_in,
                              void* d_out, int out_size) {
    const float* inp = (const float*)d_in[0];
    const float* tgt = (const float*)d_in[1];
    if (n_in >= 2 && in_sizes[0] < in_sizes[1]) {   // defensive: input is the big one
        const float* tmp = inp; inp = tgt; tgt = tmp;
    }

    yolo_zero_kernel<<<(NCELL / 16 + 255) / 256, 256>>>();
    yolo_build_kernel<<<1, 32>>>(tgt);
    yolo_main_kernel<<<NBLK, TPB>>>(inp);
    yolo_final_kernel<<<1, 256>>>((float*)d_out, out_size);
}

// round 7
// speedup vs baseline: 1.1653x; 1.1653x over previous
#include <cuda_runtime.h>
#include <math.h>

// Problem constants
#define Bc 16
#define Ac 3
#define Cc 80
#define Hc 76
#define Wc 76
#define Tc 50
#define Sc (Hc * Wc)            // 5776
#define NCELL (Bc * Ac * Sc)    // 277248
#define NCH 85

#define TPB2 256
#define NB2  272                // main grid; stride = 69632, 4 iters/thread

// ---------------------------------------------------------------------------
// Scratch (device globals, no allocation)
// g_tag[i] = (epoch << 2) | (noobj_suppressed << 1) | mask
// Stale entries (old epoch) read as flags=0, so no zeroing pass is needed.
// ---------------------------------------------------------------------------
__device__ unsigned g_epoch = 0;
__device__ unsigned g_done  = 0;
__device__ __align__(16) unsigned g_tag[NCELL];
__device__ float g_tx[NCELL];
__device__ float g_ty[NCELL];
__device__ float g_tw[NCELL];
__device__ float g_th[NCELL];
__device__ unsigned g_cls[NCELL * 3];        // class bitmask, lazily cleared
__device__ float g_part[NB2 * 9];            // per-block partials

// softplus(x) = log(1 + e^x), stable, fast-math (MUFU EX2/LG2).
// bce(sigmoid(x), t) == softplus(x) - t*x  (clip(-100) unreachable for
// finite normal logits: needs |x| > 100).
__device__ __forceinline__ float softplusf(float x) {
    float e = __expf(-fabsf(x));
    return fmaxf(x, 0.0f) + __logf(1.0f + e);
}

// ---------------------------------------------------------------------------
// Kernel 1: build targets. Targets staged through SMEM (coalesced) to break
// the serial DRAM-latency chain; threads 0..15 then process their batch
// serially over t (last-wins matches XLA serial scatter-set). Cells are
// disjoint across batches (flat index contains b) -> no atomics.
// ---------------------------------------------------------------------------
__global__ void yolo_build_kernel(const float* __restrict__ tgt) {
    __shared__ float s[Bc * Tc * 5];         // 4000 floats = 16 KB
    __shared__ unsigned sh_e;

    for (int i = threadIdx.x; i < Bc * Tc * 5; i += blockDim.x)
        s[i] = tgt[i];
    if (threadIdx.x == 0) {
        unsigned e = g_epoch + 1;
        g_epoch = e;
        sh_e = e;
    }
    __syncthreads();

    int b = threadIdx.x;
    if (b >= Bc) return;
    const unsigned epoch = sh_e;

    // SA = ANCHORS / 8 (exact in binary)
    const float aw[3] = {1.25f, 2.0f, 4.125f};
    const float ah[3] = {1.625f, 3.75f, 2.875f};

    for (int t = 0; t < Tc; t++) {
        const float* r = s + (b * Tc + t) * 5;
        float c0 = r[0], c1 = r[1], c2 = r[2], c3 = r[3], c4 = r[4];
        if ((c0 + c1 + c2 + c3 + c4) == 0.0f) continue;   // valid check

        int   cls = (int)c0;
        float gx = c1 * (float)Wc;
        float gy = c2 * (float)Hc;
        float gw = c3 * (float)Wc;
        float gh = c4 * (float)Hc;
        int gi = (int)gx;
        int gj = (int)gy;

        // IoU vs anchors (+1 shift as in reference), first-max-wins argmax
        float a1 = (gw + 1.0f) * (gh + 1.0f);
        float iou[3];
        int best = 0;
        #pragma unroll
        for (int a = 0; a < 3; a++) {
            float iw = fmaxf(fminf(gw, aw[a]) + 1.0f, 0.0f);
            float ih = fmaxf(fminf(gh, ah[a]) + 1.0f, 0.0f);
            float inter = iw * ih;
            float a2 = (aw[a] + 1.0f) * (ah[a] + 1.0f);
            iou[a] = inter / (a1 + a2 - inter + 1e-16f);
            if (iou[a] > iou[best]) best = a;
        }

        // noobj suppression: valid & iou > 0.5 (drop-mode flat bounds)
        #pragma unroll
        for (int a = 0; a < 3; a++) {
            if (iou[a] > 0.5f) {
                long long idx = (((long long)(b * Ac + a) * Hc + gj) * Wc + gi);
                if (idx >= 0 && idx < NCELL) {
                    int ci = (int)idx;
                    unsigned cur = g_tag[ci];
                    unsigned fl = ((cur >> 2) == epoch) ? (cur & 3u) : 0u;
                    g_tag[ci] = (epoch << 2) | fl | 2u;
                }
            }
        }

        // positive assignment (ok = valid & gj<H & gi<W; drop-mode bounds)
        if (gj < Hc && gi < Wc) {
            long long cell = (((long long)(b * Ac + best) * Hc + gj) * Wc + gi);
            if (cell >= 0 && cell < NCELL) {
                int ci = (int)cell;
                unsigned cur = g_tag[ci];
                unsigned fl = ((cur >> 2) == epoch) ? (cur & 3u) : 0u;
                if (!(fl & 1u)) {            // first mask hit this launch:
                    g_cls[ci * 3 + 0] = 0u;  // lazy-clear class bits
                    g_cls[ci * 3 + 1] = 0u;
                    g_cls[ci * 3 + 2] = 0u;
                }
                g_tag[ci] = (epoch << 2) | fl | 1u;
                g_tx[ci] = gx - (float)gi;
                g_ty[ci] = gy - (float)gj;
                g_tw[ci] = logf(gw / aw[best] + 1e-16f);   // accurate log, 800 calls
                g_th[ci] = logf(gh / ah[best] + 1e-16f);
                long long cidx = cell * Cc + cls;
                if (cidx >= 0 && cidx < (long long)NCELL * Cc && cls >= 0 && cls < Cc)
                    g_cls[ci * 3 + (cls >> 5)] |= (1u << (cls & 31));
            }
        }
    }
}

// ---------------------------------------------------------------------------
// Kernel 2: main. Grid-stride over cells; only channel 4 read everywhere,
// channels 0-3 / 5-84 only at ~800 masked cells. Warp-shuffle reduction
// (1 barrier), fused deterministic final reduce via last-block ticket.
// Slots: 0=sum_noobj_bce 1=n_noobj 2=x 3=y 4=w 5=h 6=conf_obj 7=cls 8=n_mask
// ---------------------------------------------------------------------------
__global__ void __launch_bounds__(TPB2) yolo_main_kernel(
        const float* __restrict__ inp, float* __restrict__ out, int out_size) {
    const unsigned epoch = g_epoch;
    float v[9];
    #pragma unroll
    for (int k = 0; k < 9; k++) v[k] = 0.0f;

    const int stride = NB2 * TPB2;
    for (int i = blockIdx.x * TPB2 + threadIdx.x; i < NCELL; i += stride) {
        int g  = i / Sc;             // b*A + a
        int hw = i - g * Sc;
        const float* base = inp + (size_t)g * NCH * Sc + hw;

        float x4 = base[4 * Sc];     // conf logit (coalesced)
        unsigned tag = g_tag[i];
        unsigned fl = ((tag >> 2) == epoch) ? (tag & 3u) : 0u;

        if (!(fl & 2u)) {                       // noobj = 1 here
            v[0] += softplusf(x4);              // bce(conf, 0)
            v[1] += 1.0f;
        }
        if (fl & 1u) {                          // masked cell (~800 total)
            v[8] += 1.0f;
            float x0 = base[0];
            float x1 = base[Sc];
            float x2 = base[2 * Sc];
            float x3 = base[3 * Sc];
            v[2] += softplusf(x0) - g_tx[i] * x0;
            v[3] += softplusf(x1) - g_ty[i] * x1;
            float dw = x2 - g_tw[i]; v[4] += dw * dw;
            float dh = x3 - g_th[i]; v[5] += dh * dh;
            v[6] += softplusf(-x4);             // bce(conf, 1)

            unsigned cb0 = g_cls[i * 3 + 0];
            unsigned cb1 = g_cls[i * 3 + 1];
            unsigned cb2 = g_cls[i * 3 + 2];
            float sc = 0.0f, sel = 0.0f;
            #pragma unroll 4
            for (int c = 0; c < Cc; c++) {
                float xc = base[(5 + c) * Sc];
                unsigned word = (c < 32) ? cb0 : (c < 64) ? cb1 : cb2;
                sc += softplusf(xc);
                if ((word >> (c & 31)) & 1u) sel += xc;
            }
            v[7] += sc - sel;
        }
    }

    // Warp shuffle reduce (deterministic)
    #pragma unroll
    for (int k = 0; k < 9; k++)
        #pragma unroll
        for (int off = 16; off > 0; off >>= 1)
            v[k] += __shfl_down_sync(0xffffffffu, v[k], off);

    __shared__ float swarp[TPB2 / 32][9];
    int lane = threadIdx.x & 31;
    int wid  = threadIdx.x >> 5;
    if (lane == 0)
        #pragma unroll
        for (int k = 0; k < 9; k++) swarp[wid][k] = v[k];
    __syncthreads();

    if (wid == 0) {
        float a[9];
        #pragma unroll
        for (int k = 0; k < 9; k++)
            a[k] = (lane < TPB2 / 32) ? swarp[lane][k] : 0.0f;
        #pragma unroll
        for (int k = 0; k < 9; k++)
            #pragma unroll
            for (int off = 4; off > 0; off >>= 1)
                a[k] += __shfl_down_sync(0xffffffffu, a[k], off);
        if (lane == 0)
            #pragma unroll
            for (int k = 0; k < 9; k++) g_part[blockIdx.x * 9 + k] = a[k];
    }

    // Last-block ticket (threadFenceReduction pattern)
    __shared__ int is_last;
    __threadfence();
    if (threadIdx.x == 0) {
        unsigned t = atomicAdd(&g_done, 1u);
        is_last = (t == NB2 - 1);
        if (is_last) g_done = 0;                 // reset for next replay
    }
    __syncthreads();

    if (is_last && threadIdx.x < 32) {
        float a[9];
        #pragma unroll
        for (int k = 0; k < 9; k++) a[k] = 0.0f;
        for (int j = threadIdx.x; j < NB2; j += 32)
            #pragma unroll
            for (int k = 0; k < 9; k++) a[k] += __ldcg(&g_part[j * 9 + k]);
        #pragma unroll
        for (int k = 0; k < 9; k++)
            #pragma unroll
            for (int off = 16; off > 0; off >>= 1)
                a[k] += __shfl_down_sync(0xffffffffu, a[k], off);

        if (threadIdx.x == 0) {
            const float N = (float)NCELL;
            float n_m  = a[8];
            float n_nm = a[1];
            float loss_x = a[2] / N / n_m;
            float loss_y = a[3] / N / n_m;
            float loss_w = a[4] / N / n_m;
            float loss_h = a[5] / N / n_m;
            float loss_conf = a[6] / N / n_m + 0.5f * a[0] / N / n_nm;
            float loss_cls  = a[7] / (n_m * (float)Cc) / n_m;
            float loss = 2.5f * (loss_x + loss_y) + 2.5f * (loss_w + loss_h)
                       + loss_conf + loss_cls;
            float res[7] = {loss, loss_x, loss_y, loss_w, loss_h,
                            loss_conf, loss_cls};
            for (int k = 0; k < 7 && k < out_size; k++) out[k] = res[k];
        }
    }
}

// ---------------------------------------------------------------------------
extern "C" void kernel_launch(void* const* d_in, const int* in_sizes, int n_in,
                              void* d_out, int out_size) {
    const float* inp = (const float*)d_in[0];
    const float* tgt = (const float*)d_in[1];
    if (n_in >= 2 && in_sizes[0] < in_sizes[1]) {   // defensive
        const float* tmp = inp; inp = tgt; tgt = tmp;
    }

    yolo_build_kernel<<<1, 256>>>(tgt);
    yolo_main_kernel<<<NB2, TPB2>>>(inp, (float*)d_out, out_size);
}

// round 8
// speedup vs baseline: 1.7661x; 1.5155x over previous
#include <cuda_runtime.h>
#include <math.h>

// Problem constants
#define Bc 16
#define Ac 3
#define Cc 80
#define Hc 76
#define Wc 76
#define Tc 50
#define Sc (Hc * Wc)            // 5776
#define NCELL (Bc * Ac * Sc)    // 277248
#define NCH 85
#define NT (Bc * Tc)            // 800 targets
#define NSUPW (NCELL / 32)      // 8664 bitmask words (exact)

#define TPB 256
#define NB (NCELL / TPB)        // 1083 blocks, exact: NCELL = 1083*256

#define KINV 0xFFFFFFFFu

// ---------------------------------------------------------------------------
// Scratch (device globals, no allocation)
// ---------------------------------------------------------------------------
__device__ unsigned g_sup[NSUPW];     // suppression bitmask (noobj=0 cells)
__device__ unsigned g_ekey[NT];       // (cell<<7)|cls, or KINV
__device__ unsigned g_eflag[NT];      // bit0 = winner (last per cell), bit1 = first (cell,cls)
__device__ float4   g_evals[NT];      // tx,ty,tw,th
__device__ float    g_part[NB * 9];   // per-block partials
__device__ unsigned g_done = 0;

// softplus via MUFU intrinsics. bce(sigmoid(x), t) == softplus(x) - t*x
// (reference clip(-100) unreachable for finite normal logits).
__device__ __forceinline__ float softplusf(float x) {
    return fmaxf(x, 0.0f) + __logf(1.0f + __expf(-fabsf(x)));
}

// ---------------------------------------------------------------------------
// Kernel 1: build. One block.
//  phase 0: zero suppression bits; stage targets in SMEM.
//  phase 1: lanes 0..15 (one per batch) serially process 50 targets entirely
//           in SMEM (no global RMW chains); emit fire-and-forget RED.OR for
//           noobj suppression.
//  phase 2: 256 threads in parallel compute winner / first-pair flags
//           (O(50) scan per entry) and export compact entry records.
// Cells are batch-disjoint, so cross-batch races don't exist; atomicOr on
// the shared bitmask handles any same-word collisions.
// ---------------------------------------------------------------------------
__global__ void __launch_bounds__(TPB) yolo_build_kernel(const float* __restrict__ tgt) {
    __shared__ float    s[NT * 5];        // 16 KB staged targets
    __shared__ unsigned skey[NT];         // packed (cell<<7)|cls or KINV
    __shared__ float    stx[NT], sty[NT], stw[NT], sth[NT];

    int tid = threadIdx.x;
    for (int i = tid; i < NSUPW; i += TPB) g_sup[i] = 0u;
    for (int i = tid; i < NT * 5; i += TPB) s[i] = tgt[i];
    __syncthreads();

    if (tid < Bc) {
        int b = tid;
        // SA = ANCHORS / (608/76) = ANCHORS / 8 (exact in binary)
        const float aw[3] = {1.25f, 2.0f, 4.125f};
        const float ah[3] = {1.625f, 3.75f, 2.875f};

        for (int t = 0; t < Tc; t++) {
            int e = b * Tc + t;
            const float* r = s + e * 5;
            float c0 = r[0], c1 = r[1], c2 = r[2], c3 = r[3], c4 = r[4];
            unsigned key = KINV;
            if ((c0 + c1 + c2 + c3 + c4) != 0.0f) {     // valid
                int   cls = (int)c0;
                float gx = c1 * (float)Wc;
                float gy = c2 * (float)Hc;
                float gw = c3 * (float)Wc;
                float gh = c4 * (float)Hc;
                int gi = (int)gx;
                int gj = (int)gy;

                // IoU vs anchors (+1 shift), first-max-wins argmax
                float a1 = (gw + 1.0f) * (gh + 1.0f);
                float iou[3];
                int best = 0;
                #pragma unroll
                for (int a = 0; a < 3; a++) {
                    float iw = fmaxf(fminf(gw, aw[a]) + 1.0f, 0.0f);
                    float ih = fmaxf(fminf(gh, ah[a]) + 1.0f, 0.0f);
                    float inter = iw * ih;
                    float a2 = (aw[a] + 1.0f) * (ah[a] + 1.0f);
                    iou[a] = inter / (a1 + a2 - inter + 1e-16f);
                    if (iou[a] > iou[best]) best = a;
                }

                // noobj suppression: valid & iou>0.5 (drop-mode flat bounds)
                #pragma unroll
                for (int a = 0; a < 3; a++) {
                    if (iou[a] > 0.5f) {
                        long long idx = (((long long)(b * Ac + a) * Hc + gj) * Wc + gi);
                        if (idx >= 0 && idx < NCELL) {
                            int ii = (int)idx;
                            atomicOr(&g_sup[ii >> 5], 1u << (ii & 31));  // RED.OR
                        }
                    }
                }

                // positive assignment (ok = valid & gj<H & gi<W; drop bounds)
                if (gj < Hc && gi < Wc) {
                    long long cell = (((long long)(b * Ac + best) * Hc + gj) * Wc + gi);
                    if (cell >= 0 && cell < NCELL && cls >= 0 && cls < Cc) {
                        key = ((unsigned)cell << 7) | (unsigned)cls;
                        stx[e] = gx - (float)gi;
                        sty[e] = gy - (float)gj;
                        stw[e] = logf(gw / aw[best] + 1e-16f);
                        sth[e] = logf(gh / ah[best] + 1e-16f);
                    }
                }
            }
            skey[e] = key;
            if (key == KINV) { stx[e] = 0.f; sty[e] = 0.f; stw[e] = 0.f; sth[e] = 0.f; }
        }
    }
    __syncthreads();

    // phase 2: flags + export (parallel, independent SMEM loads)
    for (int e = tid; e < NT; e += TPB) {
        unsigned k = skey[e];
        unsigned fl = 0u;
        if (k != KINV) {
            int base = (e / Tc) * Tc;
            unsigned mycell = k >> 7;
            bool win = true, first = true;
            #pragma unroll 5
            for (int t2 = 0; t2 < Tc; t2++) {
                unsigned k2 = skey[base + t2];
                bool samecell = (k2 != KINV) && ((k2 >> 7) == mycell);
                int e2 = base + t2;
                if (e2 > e && samecell) win = false;     // later target owns cell
                if (e2 < e && k2 == k)  first = false;   // earlier identical pair
            }
            fl = (win ? 1u : 0u) | (first ? 2u : 0u);
        }
        g_ekey[e] = k;
        g_eflag[e] = fl;
        g_evals[e] = make_float4(stx[e], sty[e], stw[e], sth[e]);
    }
}

// ---------------------------------------------------------------------------
// Kernel 2: main. Exactly NCELL threads (1083 x 256, one full wave).
// Every thread: conf logit + suppression bit (noobj term).
// Threads 0..799 additionally evaluate their target entry (masked-cell terms).
// Deterministic warp/block tree reduce + last-block ticket final combine.
// Slots: 0=noobj_bce 1=n_noobj 2=x 3=y 4=w 5=h 6=conf_obj 7=cls 8=n_mask
// ---------------------------------------------------------------------------
__global__ void __launch_bounds__(TPB) yolo_main_kernel(
        const float* __restrict__ inp, float* __restrict__ out, int out_size) {
    int i = blockIdx.x * TPB + threadIdx.x;
    float v[9];
    #pragma unroll
    for (int k = 0; k < 9; k++) v[k] = 0.0f;

    // --- per-cell noobj term (i < NCELL always: grid is exact) ---
    {
        int g  = i / Sc;
        int hw = i - g * Sc;
        float x4 = inp[(size_t)g * NCH * Sc + 4 * Sc + hw];   // coalesced
        unsigned w = g_sup[i >> 5];                            // warp-broadcast
        if (!((w >> (i & 31)) & 1u)) {
            v[0] = softplusf(x4);     // bce(conf, 0)
            v[1] = 1.0f;
        }
    }

    // --- per-entry masked terms (threads 0..799 only) ---
    if (i < NT) {
        unsigned k = g_ekey[i];
        if (k != KINV) {
            unsigned fl = g_eflag[i];
            int cell = (int)(k >> 7);
            int cls  = (int)(k & 127u);
            int g  = cell / Sc;
            int hw = cell - g * Sc;
            const float* base = inp + (size_t)g * NCH * Sc + hw;

            if (fl & 2u)                      // distinct (cell,cls): -t_c * x_c
                v[7] -= base[(5 + cls) * Sc];

            if (fl & 1u) {                    // cell winner: full cell losses
                float4 tv = g_evals[i];
                float x0 = base[0];
                float x1 = base[Sc];
                float x2 = base[2 * Sc];
                float x3 = base[3 * Sc];
                float x4 = base[4 * Sc];
                v[2] = softplusf(x0) - tv.x * x0;
                v[3] = softplusf(x1) - tv.y * x1;
                float dw = x2 - tv.z; v[4] = dw * dw;
                float dh = x3 - tv.w; v[5] = dh * dh;
                v[6] = softplusf(-x4);        // bce(conf, 1)
                v[8] = 1.0f;
                float sc = 0.0f;
                #pragma unroll 8
                for (int c = 0; c < Cc; c++)  // independent loads -> high MLP
                    sc += softplusf(base[(5 + c) * Sc]);
                v[7] += sc;
            }
        }
    }

    // --- deterministic block reduce ---
    int lane = threadIdx.x & 31;
    int wid  = threadIdx.x >> 5;
    #pragma unroll
    for (int k = 0; k < 9; k++)
        #pragma unroll
        for (int off = 16; off > 0; off >>= 1)
            v[k] += __shfl_down_sync(0xffffffffu, v[k], off);

    __shared__ float swarp[TPB / 32][9];
    if (lane == 0)
        #pragma unroll
        for (int k = 0; k < 9; k++) swarp[wid][k] = v[k];
    __syncthreads();

    if (wid == 0) {
        float a[9];
        #pragma unroll
        for (int k = 0; k < 9; k++)
            a[k] = (lane < TPB / 32) ? swarp[lane][k] : 0.0f;
        #pragma unroll
        for (int k = 0; k < 9; k++)
            #pragma unroll
            for (int off = 4; off > 0; off >>= 1)
                a[k] += __shfl_down_sync(0xffffffffu, a[k], off);
        if (lane == 0)
            #pragma unroll
            for (int k = 0; k < 9; k++) g_part[blockIdx.x * 9 + k] = a[k];
    }

    // --- last-block ticket (threadFenceReduction pattern) ---
    __shared__ int is_last;
    __threadfence();
    if (threadIdx.x == 0) {
        unsigned t = atomicAdd(&g_done, 1u);
        is_last = (t == NB - 1);
        if (is_last) g_done = 0;              // reset for next replay
    }
    __syncthreads();

    if (is_last) {
        float a[9];
        #pragma unroll
        for (int k = 0; k < 9; k++) a[k] = 0.0f;
        for (int j = threadIdx.x; j < NB; j += TPB)
            #pragma unroll
            for (int k = 0; k < 9; k++) a[k] += __ldcg(&g_part[j * 9 + k]);

        #pragma unroll
        for (int k = 0; k < 9; k++)
            #pragma unroll
            for (int off = 16; off > 0; off >>= 1)
                a[k] += __shfl_down_sync(0xffffffffu, a[k], off);
        if (lane == 0)
            #pragma unroll
            for (int k = 0; k < 9; k++) swarp[wid][k] = a[k];
        __syncthreads();

        if (threadIdx.x == 0) {
            float tot[9];
            #pragma unroll
            for (int k = 0; k < 9; k++) {
                float t = 0.0f;
                #pragma unroll
                for (int w2 = 0; w2 < TPB / 32; w2++) t += swarp[w2][k];
                tot[k] = t;
            }
            const float N = (float)NCELL;
            float n_m  = tot[8];
            float n_nm = tot[1];
            float loss_x = tot[2] / N / n_m;
            float loss_y = tot[3] / N / n_m;
            float loss_w = tot[4] / N / n_m;
            float loss_h = tot[5] / N / n_m;
            float loss_conf = tot[6] / N / n_m + 0.5f * tot[0] / N / n_nm;
            float loss_cls  = tot[7] / (n_m * (float)Cc) / n_m;
            float loss = 2.5f * (loss_x + loss_y) + 2.5f * (loss_w + loss_h)
                       + loss_conf + loss_cls;
            float res[7] = {loss, loss_x, loss_y, loss_w, loss_h,
                            loss_conf, loss_cls};
            for (int k = 0; k < 7 && k < out_size; k++) out[k] = res[k];
        }
    }
}

// ---------------------------------------------------------------------------
extern "C" void kernel_launch(void* const* d_in, const int* in_sizes, int n_in,
                              void* d_out, int out_size) {
    const float* inp = (const float*)d_in[0];
    const float* tgt = (const float*)d_in[1];
    if (n_in >= 2 && in_sizes[0] < in_sizes[1]) {   // defensive
        const float* tmp = inp; inp = tgt; tgt = tmp;
    }

    yolo_build_kernel<<<1, TPB>>>(tgt);
    yolo_main_kernel<<<NB, TPB>>>(inp, (float*)d_out, out_size);
}

// round 10
// speedup vs baseline: 3.6754x; 2.0811x over previous
#include <cuda_runtime.h>
#include <math.h>

// Problem constants
#define Bc 16
#define Ac 3
#define Cc 80
#define Hc 76
#define Wc 76
#define Tc 50
#define Sc (Hc * Wc)            // 5776 (divisible by 4)
#define NCELL (Bc * Ac * Sc)    // 277248
#define NCH 85
#define NT (Bc * Tc)            // 800 targets
#define NSUPW (NCELL / 32)      // 8664 suppression words (exact)

#define TPB 256
#define NQ (NCELL / 4)          // 69312 float4 cells
#define NB ((NQ + TPB - 1) / TPB)   // 271 blocks

#define BTPB 800                // build threads: one per target

#define KINV 0xFFFFFFFFu

// ---------------------------------------------------------------------------
// Scratch (device globals, no allocation)
// ---------------------------------------------------------------------------
__device__ unsigned g_sup[NSUPW];     // suppression bitmask (noobj=0 cells)
__device__ unsigned g_ekey[NT];       // (cell<<7)|cls, or KINV
__device__ unsigned g_eflag[NT];      // bit0 = winner (last per cell), bit1 = first (cell,cls)
__device__ float4   g_evals[NT];      // tx,ty,tw,th
__device__ float    g_part[NB * 9];   // per-block partials
__device__ unsigned g_done = 0;

// softplus via MUFU intrinsics. bce(sigmoid(x), t) == softplus(x) - t*x
// (reference clip(-100) unreachable for finite normal logits).
__device__ __forceinline__ float softplusf(float x) {
    return fmaxf(x, 0.0f) + __logf(1.0f + __expf(-fabsf(x)));
}

// ---------------------------------------------------------------------------
// Kernel 1: build. One block, 800 threads — ONE THREAD PER TARGET.
// Per-target work is independent (suppression OR is idempotent); the
// order-dependent winner/first flags come from the parallel phase-C scan,
// so no serial loop anywhere.
// ---------------------------------------------------------------------------
__global__ void __launch_bounds__(BTPB) yolo_build_kernel(const float* __restrict__ tgt) {
    __shared__ float    s[NT * 5];        // 16 KB staged targets
    __shared__ unsigned skey[NT];         // packed (cell<<7)|cls or KINV
    __shared__ float4   svals[NT];

    int e = threadIdx.x;                  // target index, 0..799

    // phase A: zero suppression bits + stage targets (coalesced)
    for (int i = e; i < NSUPW; i += BTPB) g_sup[i] = 0u;
    for (int i = e; i < NT * 5; i += BTPB) s[i] = tgt[i];
    __syncthreads();

    // phase B: per-target compute (fully parallel)
    {
        // SA = ANCHORS / (608/76) = ANCHORS / 8 (exact in binary)
        const float aw[3] = {1.25f, 2.0f, 4.125f};
        const float ah[3] = {1.625f, 3.75f, 2.875f};

        int b = e / Tc;
        const float* r = s + e * 5;
        float c0 = r[0], c1 = r[1], c2 = r[2], c3 = r[3], c4 = r[4];
        unsigned key = KINV;
        float4 tv = make_float4(0.f, 0.f, 0.f, 0.f);

        if ((c0 + c1 + c2 + c3 + c4) != 0.0f) {      // valid
            int   cls = (int)c0;
            float gx = c1 * (float)Wc;
            float gy = c2 * (float)Hc;
            float gw = c3 * (float)Wc;
            float gh = c4 * (float)Hc;
            int gi = (int)gx;
            int gj = (int)gy;

            // IoU vs anchors (+1 shift), first-max-wins argmax
            float a1 = (gw + 1.0f) * (gh + 1.0f);
            float iou[3];
            int best = 0;
            #pragma unroll
            for (int a = 0; a < 3; a++) {
                float iw = fmaxf(fminf(gw, aw[a]) + 1.0f, 0.0f);
                float ih = fmaxf(fminf(gh, ah[a]) + 1.0f, 0.0f);
                float inter = iw * ih;
                float a2 = (aw[a] + 1.0f) * (ah[a] + 1.0f);
                iou[a] = inter / (a1 + a2 - inter + 1e-16f);
                if (iou[a] > iou[best]) best = a;
            }

            // noobj suppression: valid & iou>0.5 (drop-mode flat bounds),
            // fire-and-forget RED.OR, idempotent -> order-free
            #pragma unroll
            for (int a = 0; a < 3; a++) {
                if (iou[a] > 0.5f) {
                    long long idx = (((long long)(b * Ac + a) * Hc + gj) * Wc + gi);
                    if (idx >= 0 && idx < NCELL) {
                        int ii = (int)idx;
                        atomicOr(&g_sup[ii >> 5], 1u << (ii & 31));
                    }
                }
            }

            // positive assignment (ok = valid & gj<H & gi<W; drop bounds)
            if (gj < Hc && gi < Wc) {
                long long cell = (((long long)(b * Ac + best) * Hc + gj) * Wc + gi);
                if (cell >= 0 && cell < NCELL && cls >= 0 && cls < Cc) {
                    key = ((unsigned)cell << 7) | (unsigned)cls;
                    tv.x = gx - (float)gi;
                    tv.y = gy - (float)gj;
                    tv.z = logf(gw / aw[best] + 1e-16f);
                    tv.w = logf(gh / ah[best] + 1e-16f);
                }
            }
        }
        skey[e] = key;
        svals[e] = tv;
    }
    __syncthreads();

    // phase C: winner / first-pair flags via parallel scan over own batch
    {
        unsigned k = skey[e];
        unsigned fl = 0u;
        if (k != KINV) {
            int base = (e / Tc) * Tc;
            unsigned mycell = k >> 7;
            bool win = true, first = true;
            #pragma unroll 5
            for (int t2 = 0; t2 < Tc; t2++) {
                int e2 = base + t2;
                unsigned k2 = skey[e2];
                bool samecell = (k2 != KINV) && ((k2 >> 7) == mycell);
                if (e2 > e && samecell) win = false;     // later target owns cell
                if (e2 < e && k2 == k)  first = false;   // earlier identical pair
            }
            fl = (win ? 1u : 0u) | (first ? 2u : 0u);
        }
        g_ekey[e] = k;
        g_eflag[e] = fl;
        g_evals[e] = svals[e];
    }
}

// ---------------------------------------------------------------------------
// Kernel 2: main. One thread per 4 cells (float4 conf load, same g for all
// four since Sc % 4 == 0). Threads 0..799 additionally evaluate their target
// entry. Deterministic reduce + last-block ticket final combine.
// Slots: 0=noobj_bce 1=n_noobj 2=x 3=y 4=w 5=h 6=conf_obj 7=cls 8=n_mask
// ---------------------------------------------------------------------------
__global__ void __launch_bounds__(TPB) yolo_main_kernel(
        const float* __restrict__ inp, float* __restrict__ out, int out_size) {
    int i4 = blockIdx.x * TPB + threadIdx.x;
    float v[9];
    #pragma unroll
    for (int k = 0; k < 9; k++) v[k] = 0.0f;

    // --- per-cell noobj term, 4 cells per thread ---
    if (i4 < NQ) {
        int cell0 = i4 * 4;
        int g  = cell0 / Sc;
        int hw = cell0 - g * Sc;          // multiple of 4 within channel
        const float4 c4 = *reinterpret_cast<const float4*>(
            inp + (size_t)g * NCH * Sc + 4 * Sc + hw);
        unsigned w  = g_sup[cell0 >> 5];
        unsigned sh = (unsigned)cell0 & 31u;   // 4-aligned within word
        float cj[4] = {c4.x, c4.y, c4.z, c4.w};
        #pragma unroll
        for (int j = 0; j < 4; j++) {
            if (!((w >> (sh + j)) & 1u)) {
                v[0] += softplusf(cj[j]);     // bce(conf, 0)
                v[1] += 1.0f;
            }
        }
    }

    // --- per-entry masked terms (threads 0..799) ---
    if (i4 < NT) {
        unsigned k = g_ekey[i4];
        if (k != KINV) {
            unsigned fl = g_eflag[i4];
            int cell = (int)(k >> 7);
            int cls  = (int)(k & 127u);
            int g  = cell / Sc;
            int hw = cell - g * Sc;
            const float* base = inp + (size_t)g * NCH * Sc + hw;

            if (fl & 2u)                      // distinct (cell,cls): -t_c * x_c
                v[7] -= base[(5 + cls) * Sc];

            if (fl & 1u) {                    // cell winner: full cell losses
                float4 tv = g_evals[i4];
                float x0 = base[0];
                float x1 = base[Sc];
                float x2 = base[2 * Sc];
                float x3 = base[3 * Sc];
                float x4 = base[4 * Sc];
                v[2] = softplusf(x0) - tv.x * x0;
                v[3] = softplusf(x1) - tv.y * x1;
                float dw = x2 - tv.z; v[4] = dw * dw;
                float dh = x3 - tv.w; v[5] = dh * dh;
                v[6] = softplusf(-x4);        // bce(conf, 1)
                v[8] = 1.0f;
                float sc = 0.0f;
                #pragma unroll 8
                for (int c = 0; c < Cc; c++)  // independent loads -> high MLP
                    sc += softplusf(base[(5 + c) * Sc]);
                v[7] += sc;
            }
        }
    }

    // --- deterministic block reduce ---
    int lane = threadIdx.x & 31;
    int wid  = threadIdx.x >> 5;
    #pragma unroll
    for (int k = 0; k < 9; k++)
        #pragma unroll
        for (int off = 16; off > 0; off >>= 1)
            v[k] += __shfl_down_sync(0xffffffffu, v[k], off);

    __shared__ float swarp[TPB / 32][9];
    if (lane == 0)
        #pragma unroll
        for (int k = 0; k < 9; k++) swarp[wid][k] = v[k];
    __syncthreads();

    if (wid == 0) {
        float a[9];
        #pragma unroll
        for (int k = 0; k < 9; k++)
            a[k] = (lane < TPB / 32) ? swarp[lane][k] : 0.0f;
        #pragma unroll
        for (int k = 0; k < 9; k++)
            #pragma unroll
            for (int off = 4; off > 0; off >>= 1)
                a[k] += __shfl_down_sync(0xffffffffu, a[k], off);
        if (lane == 0)
            #pragma unroll
            for (int k = 0; k < 9; k++) g_part[blockIdx.x * 9 + k] = a[k];
    }

    // --- last-block ticket (threadFenceReduction pattern) ---
    __shared__ int is_last;
    __threadfence();
    if (threadIdx.x == 0) {
        unsigned t = atomicAdd(&g_done, 1u);
        is_last = (t == NB - 1);
        if (is_last) g_done = 0;              // reset for next replay
    }
    __syncthreads();

    if (is_last) {
        float a[9];
        #pragma unroll
        for (int k = 0; k < 9; k++) a[k] = 0.0f;
        for (int j = threadIdx.x; j < NB; j += TPB)
            #pragma unroll
            for (int k = 0; k < 9; k++) a[k] += __ldcg(&g_part[j * 9 + k]);

        #pragma unroll
        for (int k = 0; k < 9; k++)
            #pragma unroll
            for (int off = 16; off > 0; off >>= 1)
                a[k] += __shfl_down_sync(0xffffffffu, a[k], off);
        if (lane == 0)
            #pragma unroll
            for (int k = 0; k < 9; k++) swarp[wid][k] = a[k];
        __syncthreads();

        if (threadIdx.x == 0) {
            float tot[9];
            #pragma unroll
            for (int k = 0; k < 9; k++) {
                float t = 0.0f;
                #pragma unroll
                for (int w2 = 0; w2 < TPB / 32; w2++) t += swarp[w2][k];
                tot[k] = t;
            }
            const float N = (float)NCELL;
            float n_m  = tot[8];
            float n_nm = tot[1];
            float loss_x = tot[2] / N / n_m;
            float loss_y = tot[3] / N / n_m;
            float loss_w = tot[4] / N / n_m;
            float loss_h = tot[5] / N / n_m;
            float loss_conf = tot[6] / N / n_m + 0.5f * tot[0] / N / n_nm;
            float loss_cls  = tot[7] / (n_m * (float)Cc) / n_m;
            float loss = 2.5f * (loss_x + loss_y) + 2.5f * (loss_w + loss_h)
                       + loss_conf + loss_cls;
            float res[7] = {loss, loss_x, loss_y, loss_w, loss_h,
                            loss_conf, loss_cls};
            for (int k = 0; k < 7 && k < out_size; k++) out[k] = res[k];
        }
    }
}

// ---------------------------------------------------------------------------
extern "C" void kernel_launch(void* const* d_in, const int* in_sizes, int n_in,
                              void* d_out, int out_size) {
    const float* inp = (const float*)d_in[0];
    const float* tgt = (const float*)d_in[1];
    if (n_in >= 2 && in_sizes[0] < in_sizes[1]) {   // defensive
        const float* tmp = inp; inp = tgt; tgt = tmp;
    }

    yolo_build_kernel<<<1, BTPB>>>(tgt);
    yolo_main_kernel<<<NB, TPB>>>(inp, (float*)d_out, out_size);
}

// round 11
// speedup vs baseline: 5.3195x; 1.4473x over previous
#include <cuda_runtime.h>
#include <math.h>

// Problem constants
#define Bc 16
#define Ac 3
#define Cc 80
#define Hc 76
#define Wc 76
#define Tc 50
#define Sc (Hc * Wc)            // 5776 (divisible by 4)
#define NCELL (Bc * Ac * Sc)    // 277248
#define NCH 85
#define NT (Bc * Tc)            // 800 targets
#define NSUPW (NCELL / 32)      // 8664 suppression words (exact)

#define TPB 256
#define NWARPS (TPB / 32)
#define NQ (NCELL / 4)          // 69312 float4 cells
#define NB ((NQ + TPB - 1) / TPB)   // 271 blocks -> 2168 warps >= 800 entries

#define BTPB 800                // build threads: one per target

#define KINV 0xFFFFFFFFu

// ---------------------------------------------------------------------------
// Scratch (device globals, no allocation)
// ---------------------------------------------------------------------------
__device__ unsigned g_sup[NSUPW];     // suppression bitmask (noobj=0 cells)
__device__ unsigned g_ekey[NT];       // (cell<<7)|cls, or KINV
__device__ unsigned g_eflag[NT];      // bit0 = winner (last per cell), bit1 = first (cell,cls)
__device__ float4   g_evals[NT];      // tx,ty,tw,th
__device__ float    g_part[NB * 9];   // per-block partials
__device__ unsigned g_done = 0;

// softplus via MUFU intrinsics. bce(sigmoid(x), t) == softplus(x) - t*x
// (reference clip(-100) unreachable for finite normal logits).
__device__ __forceinline__ float softplusf(float x) {
    return fmaxf(x, 0.0f) + __logf(1.0f + __expf(-fabsf(x)));
}

// ---------------------------------------------------------------------------
// Kernel 1: build. One block, 800 threads — one thread per target.
// Per-target work is independent (suppression OR is idempotent); the
// order-dependent winner/first flags come from the parallel phase-C scan.
// ---------------------------------------------------------------------------
__global__ void __launch_bounds__(BTPB) yolo_build_kernel(const float* __restrict__ tgt) {
    __shared__ float    s[NT * 5];        // 16 KB staged targets
    __shared__ unsigned skey[NT];         // packed (cell<<7)|cls or KINV
    __shared__ float4   svals[NT];

    int e = threadIdx.x;                  // target index, 0..799

    // phase A: zero suppression bits + stage targets (coalesced)
    for (int i = e; i < NSUPW; i += BTPB) g_sup[i] = 0u;
    for (int i = e; i < NT * 5; i += BTPB) s[i] = tgt[i];
    __syncthreads();

    // phase B: per-target compute (fully parallel)
    {
        // SA = ANCHORS / (608/76) = ANCHORS / 8 (exact in binary)
        const float aw[3] = {1.25f, 2.0f, 4.125f};
        const float ah[3] = {1.625f, 3.75f, 2.875f};

        int b = e / Tc;
        const float* r = s + e * 5;
        float c0 = r[0], c1 = r[1], c2 = r[2], c3 = r[3], c4 = r[4];
        unsigned key = KINV;
        float4 tv = make_float4(0.f, 0.f, 0.f, 0.f);

        if ((c0 + c1 + c2 + c3 + c4) != 0.0f) {      // valid
            int   cls = (int)c0;
            float gx = c1 * (float)Wc;
            float gy = c2 * (float)Hc;
            float gw = c3 * (float)Wc;
            float gh = c4 * (float)Hc;
            int gi = (int)gx;
            int gj = (int)gy;

            // IoU vs anchors (+1 shift), first-max-wins argmax
            float a1 = (gw + 1.0f) * (gh + 1.0f);
            float iou[3];
            int best = 0;
            #pragma unroll
            for (int a = 0; a < 3; a++) {
                float iw = fmaxf(fminf(gw, aw[a]) + 1.0f, 0.0f);
                float ih = fmaxf(fminf(gh, ah[a]) + 1.0f, 0.0f);
                float inter = iw * ih;
                float a2 = (aw[a] + 1.0f) * (ah[a] + 1.0f);
                iou[a] = inter / (a1 + a2 - inter + 1e-16f);
                if (iou[a] > iou[best]) best = a;
            }

            // noobj suppression (idempotent RED.OR, drop-mode flat bounds)
            #pragma unroll
            for (int a = 0; a < 3; a++) {
                if (iou[a] > 0.5f) {
                    long long idx = (((long long)(b * Ac + a) * Hc + gj) * Wc + gi);
                    if (idx >= 0 && idx < NCELL) {
                        int ii = (int)idx;
                        atomicOr(&g_sup[ii >> 5], 1u << (ii & 31));
                    }
                }
            }

            // positive assignment (ok = valid & gj<H & gi<W; drop bounds)
            if (gj < Hc && gi < Wc) {
                long long cell = (((long long)(b * Ac + best) * Hc + gj) * Wc + gi);
                if (cell >= 0 && cell < NCELL && cls >= 0 && cls < Cc) {
                    key = ((unsigned)cell << 7) | (unsigned)cls;
                    tv.x = gx - (float)gi;
                    tv.y = gy - (float)gj;
                    tv.z = logf(gw / aw[best] + 1e-16f);
                    tv.w = logf(gh / ah[best] + 1e-16f);
                }
            }
        }
        skey[e] = key;
        svals[e] = tv;
    }
    __syncthreads();

    // phase C: winner / first-pair flags via parallel scan over own batch
    {
        unsigned k = skey[e];
        unsigned fl = 0u;
        if (k != KINV) {
            int base = (e / Tc) * Tc;
            unsigned mycell = k >> 7;
            bool win = true, first = true;
            #pragma unroll 5
            for (int t2 = 0; t2 < Tc; t2++) {
                int e2 = base + t2;
                unsigned k2 = skey[e2];
                bool samecell = (k2 != KINV) && ((k2 >> 7) == mycell);
                if (e2 > e && samecell) win = false;     // later target owns cell
                if (e2 < e && k2 == k)  first = false;   // earlier identical pair
            }
            fl = (win ? 1u : 0u) | (first ? 2u : 0u);
        }
        g_ekey[e] = k;
        g_eflag[e] = fl;
        g_evals[e] = svals[e];
    }
}

// ---------------------------------------------------------------------------
// Kernel 2: main.
//  - Per-thread: 4 cells (float4 conf load) for the noobj term.
//  - Per-WARP: one masked-entry (global warp id < 800). The 80-class loop is
//    lane-split (c = lane, lane+32, lane+64); lane 0 handles x/y/w/h/conf;
//    contributions land in each lane's v[] and ride the normal block reduce.
//    This spreads the scattered-sector load over ~100 SMs instead of 4.
// Slots: 0=noobj_bce 1=n_noobj 2=x 3=y 4=w 5=h 6=conf_obj 7=cls 8=n_mask
// ---------------------------------------------------------------------------
__global__ void __launch_bounds__(TPB) yolo_main_kernel(
        const float* __restrict__ inp, float* __restrict__ out, int out_size) {
    int i4 = blockIdx.x * TPB + threadIdx.x;
    int lane = threadIdx.x & 31;
    int wid  = threadIdx.x >> 5;
    float v[9];
    #pragma unroll
    for (int k = 0; k < 9; k++) v[k] = 0.0f;

    // --- per-cell noobj term, 4 cells per thread ---
    if (i4 < NQ) {
        int cell0 = i4 * 4;
        int g  = cell0 / Sc;
        int hw = cell0 - g * Sc;          // multiple of 4 within channel
        const float4 c4 = *reinterpret_cast<const float4*>(
            inp + (size_t)g * NCH * Sc + 4 * Sc + hw);
        unsigned w  = g_sup[cell0 >> 5];
        unsigned sh = (unsigned)cell0 & 31u;
        float cj[4] = {c4.x, c4.y, c4.z, c4.w};
        #pragma unroll
        for (int j = 0; j < 4; j++) {
            if (!((w >> (sh + j)) & 1u)) {
                v[0] += softplusf(cj[j]);     // bce(conf, 0)
                v[1] += 1.0f;
            }
        }
    }

    // --- per-entry masked terms: ONE WARP PER ENTRY ---
    int we = blockIdx.x * NWARPS + wid;       // global warp id == entry id
    if (we < NT) {
        unsigned k = g_ekey[we];              // warp-uniform
        if (k != KINV) {
            unsigned fl = g_eflag[we];
            int cell = (int)(k >> 7);
            int cls  = (int)(k & 127u);
            int g  = cell / Sc;
            int hw = cell - g * Sc;
            const float* base = inp + (size_t)g * NCH * Sc + hw;

            if (fl & 1u) {                    // cell winner: full cell losses
                // class loop, lane-split (<=3 scattered loads per lane)
                float sc = 0.0f;
                #pragma unroll
                for (int c = lane; c < Cc; c += 32)
                    sc += softplusf(base[(5 + c) * Sc]);
                v[7] += sc;

                if (lane == 0) {
                    float4 tv = g_evals[we];
                    float x0 = base[0];
                    float x1 = base[Sc];
                    float x2 = base[2 * Sc];
                    float x3 = base[3 * Sc];
                    float x4 = base[4 * Sc];
                    v[2] += softplusf(x0) - tv.x * x0;
                    v[3] += softplusf(x1) - tv.y * x1;
                    float dw = x2 - tv.z; v[4] += dw * dw;
                    float dh = x3 - tv.w; v[5] += dh * dh;
                    v[6] += softplusf(-x4);   // bce(conf, 1)
                    v[8] += 1.0f;
                }
            }
            if ((fl & 2u) && lane == 1)       // distinct (cell,cls): -t_c*x_c
                v[7] -= base[(5 + cls) * Sc];
        }
    }

    // --- deterministic block reduce ---
    #pragma unroll
    for (int k = 0; k < 9; k++)
        #pragma unroll
        for (int off = 16; off > 0; off >>= 1)
            v[k] += __shfl_down_sync(0xffffffffu, v[k], off);

    __shared__ float swarp[NWARPS][9];
    if (lane == 0)
        #pragma unroll
        for (int k = 0; k < 9; k++) swarp[wid][k] = v[k];
    __syncthreads();

    if (wid == 0) {
        float a[9];
        #pragma unroll
        for (int k = 0; k < 9; k++)
            a[k] = (lane < NWARPS) ? swarp[lane][k] : 0.0f;
        #pragma unroll
        for (int k = 0; k < 9; k++)
            #pragma unroll
            for (int off = 4; off > 0; off >>= 1)
                a[k] += __shfl_down_sync(0xffffffffu, a[k], off);
        if (lane == 0)
            #pragma unroll
            for (int k = 0; k < 9; k++) g_part[blockIdx.x * 9 + k] = a[k];
    }

    // --- last-block ticket (threadFenceReduction pattern) ---
    __shared__ int is_last;
    __threadfence();
    if (threadIdx.x == 0) {
        unsigned t = atomicAdd(&g_done, 1u);
        is_last = (t == NB - 1);
        if (is_last) g_done = 0;              // reset for next replay
    }
    __syncthreads();

    if (is_last) {
        float a[9];
        #pragma unroll
        for (int k = 0; k < 9; k++) a[k] = 0.0f;
        for (int j = threadIdx.x; j < NB; j += TPB)
            #pragma unroll
            for (int k = 0; k < 9; k++) a[k] += __ldcg(&g_part[j * 9 + k]);

        #pragma unroll
        for (int k = 0; k < 9; k++)
            #pragma unroll
            for (int off = 16; off > 0; off >>= 1)
                a[k] += __shfl_down_sync(0xffffffffu, a[k], off);
        if (lane == 0)
            #pragma unroll
            for (int k = 0; k < 9; k++) swarp[wid][k] = a[k];
        __syncthreads();

        if (threadIdx.x == 0) {
            float tot[9];
            #pragma unroll
            for (int k = 0; k < 9; k++) {
                float t = 0.0f;
                #pragma unroll
                for (int w2 = 0; w2 < NWARPS; w2++) t += swarp[w2][k];
                tot[k] = t;
            }
            const float N = (float)NCELL;
            float n_m  = tot[8];
            float n_nm = tot[1];
            float loss_x = tot[2] / N / n_m;
            float loss_y = tot[3] / N / n_m;
            float loss_w = tot[4] / N / n_m;
            float loss_h = tot[5] / N / n_m;
            float loss_conf = tot[6] / N / n_m + 0.5f * tot[0] / N / n_nm;
            float loss_cls  = tot[7] / (n_m * (float)Cc) / n_m;
            float loss = 2.5f * (loss_x + loss_y) + 2.5f * (loss_w + loss_h)
                       + loss_conf + loss_cls;
            float res[7] = {loss, loss_x, loss_y, loss_w, loss_h,
                            loss_conf, loss_cls};
            for (int k = 0; k < 7 && k < out_size; k++) out[k] = res[k];
        }
    }
}

// ---------------------------------------------------------------------------
extern "C" void kernel_launch(void* const* d_in, const int* in_sizes, int n_in,
                              void* d_out, int out_size) {
    const float* inp = (const float*)d_in[0];
    const float* tgt = (const float*)d_in[1];
    if (n_in >= 2 && in_sizes[0] < in_sizes[1]) {   // defensive
        const float* tmp = inp; inp = tgt; tgt = tmp;
    }

    yolo_build_kernel<<<1, BTPB>>>(tgt);
    yolo_main_kernel<<<NB, TPB>>>(inp, (float*)d_out, out_size);
}